// round 9
// baseline (speedup 1.0000x reference)
#include <cuda_runtime.h>

// PCEN: s[t] = (1-c)*x[t] + c*s[t-1];  y = (x*(eps+s)^-alpha + delta)^root - delta^root
// x: [B=64, T=2048, F=128] fp32. Chunked-in-T (CT=32), float2 across F.
// 8-step warm-up (valid when c^8 <= 2^-30, runtime-checked; exact fallback).
// Software-pipelined main loop: depth-4 groups, next group prefetched during
// compute of current -> load latency hidden under the MUFU chain.

#define B_DIM   64
#define T_DIM   2048
#define F_DIM   128
#define F2      (F_DIM / 2)       // 64 float2 per timestep row
#define CT      32                // timesteps per chunk
#define NCHUNK  (T_DIM / CT)      // 64
#define WFIX    8                 // fixed warm-up steps on the fast path
#define G       4                 // pipeline group size (timesteps)
#define EPS_F   1e-6f

__device__ __forceinline__ float lg2_approx(float x) {
    float r; asm("lg2.approx.f32 %0, %1;" : "=f"(r) : "f"(x)); return r;
}
__device__ __forceinline__ float ex2_approx(float x) {
    float r; asm("ex2.approx.f32 %0, %1;" : "=f"(r) : "f"(x)); return r;
}
__device__ __forceinline__ float sqrt_approx(float x) {
    float r; asm("sqrt.approx.f32 %0, %1;" : "=f"(r) : "f"(x)); return r;
}
__device__ __forceinline__ void stg_cs_f2(float2* p, float2 v) {
    asm volatile("st.global.cs.v2.f32 [%0], {%1, %2};"
                 :: "l"(p), "f"(v.x), "f"(v.y) : "memory");
}

struct PcenP { float c, omc, nalpha, delta, root, droot; bool half_root; };

__device__ __forceinline__ float pcen_one(float xv, float s, const PcenP& p) {
    const float m = EPS_F + s;
    const float r = ex2_approx(p.nalpha * lg2_approx(m));   // (eps+s)^-alpha
    const float u = fmaf(xv, r, p.delta);
    const float o = p.half_root ? sqrt_approx(u)
                                : ex2_approx(p.root * lg2_approx(u));
    return o - p.droot;
}

__global__ __launch_bounds__(128, 10)
void pcen_kernel(const float2* __restrict__ x,
                 const float* __restrict__ alpha_p,
                 const float* __restrict__ delta_p,
                 const float* __restrict__ root_p,
                 const float* __restrict__ c_p,
                 float2* __restrict__ y)
{
    const int job   = blockIdx.x * 2 + threadIdx.y;     // 0..4095
    const int b     = job >> 6;                         // /NCHUNK
    const int chunk = job & (NCHUNK - 1);
    const int t0    = chunk * CT;
    const int f2    = threadIdx.x;                      // 0..63 coalesced

    PcenP p;
    p.c      = __ldg(c_p);
    p.omc    = 1.0f - p.c;
    p.nalpha = -__ldg(alpha_p);
    p.delta  = __ldg(delta_p);
    p.root   = __ldg(root_p);
    p.half_root = (p.root == 0.5f);
    p.droot  = p.half_root ? sqrt_approx(p.delta)
                           : ex2_approx(p.root * lg2_approx(p.delta));
    const float c = p.c, omc = p.omc;

    const float2* __restrict__ px = x + (size_t)(b * T_DIM + t0) * F2 + f2;
    float2*       __restrict__ py = y + (size_t)(b * T_DIM + t0) * F2 + f2;

    float sx = 0.f, sy = 0.f;

    // ---- Warm-up: bring EMA state to t0 (state truncation ~c^WFIX) ----
    const float l2c  = (c > 0.0f) ? lg2_approx(c) : -128.0f;
    const bool  fast = (c <= 0.0f) || (l2c * (float)WFIX <= -30.0f); // c^8 <= 2^-30

    if (fast) {
        if (t0 > 0) {
            const float2* pw = px - WFIX * F2;
            float2 w[WFIX];
            #pragma unroll
            for (int t = 0; t < WFIX; ++t) w[t] = __ldg(pw + t * F2);  // batched
            #pragma unroll
            for (int t = 0; t < WFIX; ++t) {
                sx = fmaf(c, sx, omc * w[t].x);
                sy = fmaf(c, sy, omc * w[t].y);
            }
        }
    } else {
        int W = t0;                                      // exact scan from t=0
        if (l2c < -1e-6f) {
            float w = -30.0f / l2c;
            if (w < (float)t0) W = (int)w + 1;
        }
        const float2* pw = px - (size_t)W * F2;
        for (int t = 0; t < W; ++t) {
            const float2 xv = __ldg(pw); pw += F2;
            sx = fmaf(c, sx, omc * xv.x);
            sy = fmaf(c, sy, omc * xv.y);
        }
    }

    // ---- Main chunk: software-pipelined, G timesteps per stage ----
    float2 cur[G], nxt[G];
    #pragma unroll
    for (int t = 0; t < G; ++t) cur[t] = __ldg(px + t * F2);   // prologue loads
    px += G * F2;

    #pragma unroll 1
    for (int i = 0; i < CT - G; i += G) {
        #pragma unroll
        for (int t = 0; t < G; ++t) nxt[t] = __ldg(px + t * F2);  // prefetch next
        px += G * F2;

        #pragma unroll
        for (int t = 0; t < G; ++t) {                   // compute current group
            sx = fmaf(c, sx, omc * cur[t].x);
            sy = fmaf(c, sy, omc * cur[t].y);
            float2 o;
            o.x = pcen_one(cur[t].x, sx, p);
            o.y = pcen_one(cur[t].y, sy, p);
            stg_cs_f2(py + t * F2, o);
        }
        py += G * F2;

        #pragma unroll
        for (int t = 0; t < G; ++t) cur[t] = nxt[t];    // rotate buffers
    }

    #pragma unroll
    for (int t = 0; t < G; ++t) {                       // epilogue group
        sx = fmaf(c, sx, omc * cur[t].x);
        sy = fmaf(c, sy, omc * cur[t].y);
        float2 o;
        o.x = pcen_one(cur[t].x, sx, p);
        o.y = pcen_one(cur[t].y, sy, p);
        stg_cs_f2(py + t * F2, o);
    }
}

extern "C" void kernel_launch(void* const* d_in, const int* in_sizes, int n_in,
                              void* d_out, int out_size)
{
    const float2* x      = (const float2*)d_in[0];
    const float* alpha_p = (const float*)d_in[1];
    const float* delta_p = (const float*)d_in[2];
    const float* root_p  = (const float*)d_in[3];
    const float* coef_p  = (const float*)d_in[4];
    float2* y = (float2*)d_out;

    const int jobs   = B_DIM * NCHUNK;          // 4096
    const int blocks = jobs / 2;                // 2048 (2 jobs/block)
    dim3 block(F2, 2, 1);                       // (64, 2) = 128 threads
    pcen_kernel<<<blocks, block>>>(x, alpha_p, delta_p, root_p, coef_p, y);
}